// round 3
// baseline (speedup 1.0000x reference)
#include <cuda_runtime.h>
#include <math.h>

#define DIMC 384
#define NHEADS 6
#define HD 64
#define WINS 14
#define NWIN 24
#define NW 576           // 24*24 windows
#define LW 196           // tokens per window
#define TOK (NW*LW)      // 112896
#define WH (NW*NHEADS)   // 3456
#define LL (LW*LW)       // 38416
#define HIDDEN 1536
#define LN_EPS 1e-5f
#define ATT_SCALE 0.125f // 64^-0.5

#define SCORE_SMEM ((64*200*2 + LW*WINS*2) * 4)   // 124352 B
#define AV_SMEM ((LW*HD + LL) * 4)                // 50176 + 153664 = 203840 B

// ---------------- scratch (device globals; no runtime allocation) ----------
// g_xln doubles as: LN1 output (windowed order) for QKV, then LN2 output
// (pixel order) for fc1 — LN1 output is dead after step 2.
__device__ float g_xln[(size_t)TOK * DIMC];
__device__ float g_q[(size_t)TOK * DIMC];        // [wh][p][d] head-major
__device__ float g_k[(size_t)TOK * DIMC];
__device__ float g_v[(size_t)TOK * DIMC];
__device__ float g_P[(size_t)WH * LL];           // raw attention scores
__device__ float g_attnout[(size_t)TOK * DIMC];  // windowed token order, concat heads
__device__ float g_x2[(size_t)TOK * DIMC];       // shortcut + proj (pixel order)
__device__ float g_h1[(size_t)TOK * HIDDEN];     // gelu(fc1)

// ---------------- LayerNorm ------------------------------------------------
__global__ void ln_kernel(const float* __restrict__ in, const float* __restrict__ w,
                          const float* __restrict__ b, float* __restrict__ out,
                          int windowed)
{
    int row = blockIdx.x;
    int inRow = row;
    if (windowed) {
        int wdx = row / LW, p = row % LW;
        int wy = wdx / NWIN, wx = wdx % NWIN;
        int iy = p / WINS, ix = p % WINS;
        inRow = (wy * WINS + iy) * 336 + wx * WINS + ix;
    }
    const float* xr = in + (size_t)inRow * DIMC;
    int tid = threadIdx.x;
    float v0 = xr[tid], v1 = xr[tid + 128], v2 = xr[tid + 256];
    float s = v0 + v1 + v2;
    float sq = v0 * v0 + v1 * v1 + v2 * v2;
    #pragma unroll
    for (int o = 16; o > 0; o >>= 1) {
        s  += __shfl_xor_sync(~0u, s, o);
        sq += __shfl_xor_sync(~0u, sq, o);
    }
    __shared__ float ss[4], ssq[4];
    int wid = tid >> 5, lane = tid & 31;
    if (lane == 0) { ss[wid] = s; ssq[wid] = sq; }
    __syncthreads();
    s  = ss[0] + ss[1] + ss[2] + ss[3];
    sq = ssq[0] + ssq[1] + ssq[2] + ssq[3];
    float mean = s * (1.0f / DIMC);
    float var  = sq * (1.0f / DIMC) - mean * mean;
    float inv  = rsqrtf(var + LN_EPS);
    float* orow = out + (size_t)row * DIMC;
    orow[tid]       = (v0 - mean) * inv * w[tid]       + b[tid];
    orow[tid + 128] = (v1 - mean) * inv * w[tid + 128] + b[tid + 128];
    orow[tid + 256] = (v2 - mean) * inv * w[tid + 256] + b[tid + 256];
}

__device__ __forceinline__ float gelu_exact(float v)
{
    return 0.5f * v * (1.0f + erff(v * 0.70710678118654752f));
}

// ---------------- generic fp32 GEMM, 128x128x16 tile, 8x8/thread -----------
// EPI: 1 = qkv scatter to g_q/g_k/g_v   2 = proj + residual -> g_x2 (unwindow)
//      3 = gelu -> C                    4 = +extra (residual) -> C
template <int EPI>
__global__ void __launch_bounds__(256)
sgemm(const float* __restrict__ A, const float* __restrict__ B,
      const float* __restrict__ bias, float* __restrict__ C,
      int M, int N, int K, const float* __restrict__ extra)
{
    __shared__ float As[16][128];
    __shared__ float Bs[16][128];
    int tid = threadIdx.x;
    int bn = blockIdx.x, bm = blockIdx.y;
    int tx = tid & 15, ty = tid >> 4;
    float acc[8][8] = {};

    for (int kk = 0; kk < K; kk += 16) {
        #pragma unroll
        for (int u = 0; u < 2; u++) {
            int fi = tid * 2 + u;
            int row = fi >> 2, cg = fi & 3;
            float4 va = *(const float4*)(A + (size_t)(bm * 128 + row) * K + kk + cg * 4);
            As[cg * 4 + 0][row] = va.x; As[cg * 4 + 1][row] = va.y;
            As[cg * 4 + 2][row] = va.z; As[cg * 4 + 3][row] = va.w;
        }
        #pragma unroll
        for (int u = 0; u < 2; u++) {
            int fi = tid * 2 + u;
            int row = fi >> 5, cg = fi & 31;
            float4 vb = *(const float4*)(B + (size_t)(kk + row) * N + bn * 128 + cg * 4);
            *(float4*)&Bs[row][cg * 4] = vb;
        }
        __syncthreads();
        #pragma unroll
        for (int k = 0; k < 16; k++) {
            float a[8], bb[8];
            *(float4*)(a)      = *(float4*)&As[k][ty * 8];
            *(float4*)(a + 4)  = *(float4*)&As[k][ty * 8 + 4];
            *(float4*)(bb)     = *(float4*)&Bs[k][tx * 8];
            *(float4*)(bb + 4) = *(float4*)&Bs[k][tx * 8 + 4];
            #pragma unroll
            for (int i = 0; i < 8; i++)
                #pragma unroll
                for (int j = 0; j < 8; j++)
                    acc[i][j] += a[i] * bb[j];
        }
        __syncthreads();
    }

    int m0 = bm * 128 + ty * 8, n0 = bn * 128 + tx * 8;

    if (EPI == 1) {
        int part = n0 / 384;
        int c0 = n0 % 384;
        int head = c0 / 64, d0 = c0 % 64;
        float* dst = (part == 0) ? g_q : (part == 1) ? g_k : g_v;
        #pragma unroll
        for (int i = 0; i < 8; i++) {
            int m = m0 + i;
            int wdx = m / LW, p = m % LW;
            float* drow = dst + ((size_t)(wdx * NHEADS + head) * LW + p) * HD + d0;
            #pragma unroll
            for (int j = 0; j < 8; j++)
                drow[j] = acc[i][j] + bias[n0 + j];
        }
    } else if (EPI == 2) {
        #pragma unroll
        for (int i = 0; i < 8; i++) {
            int m = m0 + i;
            int wdx = m / LW, p = m % LW;
            int wy = wdx / NWIN, wx = wdx % NWIN;
            int iy = p / WINS, ix = p % WINS;
            int pix = (wy * WINS + iy) * 336 + wx * WINS + ix;
            const float* xr = extra + (size_t)pix * DIMC;
            float* orow = g_x2 + (size_t)pix * DIMC;
            #pragma unroll
            for (int j = 0; j < 8; j++)
                orow[n0 + j] = acc[i][j] + bias[n0 + j] + xr[n0 + j];
        }
    } else if (EPI == 3) {
        #pragma unroll
        for (int i = 0; i < 8; i++) {
            int m = m0 + i;
            float* orow = C + (size_t)m * N;
            #pragma unroll
            for (int j = 0; j < 8; j++)
                orow[n0 + j] = gelu_exact(acc[i][j] + bias[n0 + j]);
        }
    } else { // EPI == 4
        #pragma unroll
        for (int i = 0; i < 8; i++) {
            int m = m0 + i;
            float* orow = C + (size_t)m * N;
            const float* xr = extra + (size_t)m * N;
            #pragma unroll
            for (int j = 0; j < 8; j++)
                orow[n0 + j] = acc[i][j] + bias[n0 + j] + xr[n0 + j];
        }
    }
}

// ---------------- attention scores: S = scale*q@k^T + rel_h + rel_w --------
__global__ void score_kernel(const float* __restrict__ rph, const float* __restrict__ rpw)
{
    extern __shared__ float sm[];
    float* qs   = sm;                 // [64][200]
    float* ks   = sm + 64 * 200;      // [64][200]
    float* relh = ks + 64 * 200;      // [196][14]
    float* relw = relh + LW * WINS;   // [196][14]

    int wh = blockIdx.x;
    int tid = threadIdx.x;
    const float* qg = g_q + (size_t)wh * LW * HD;
    const float* kg = g_k + (size_t)wh * LW * HD;

    for (int i = tid; i < LW * 16; i += 256) {
        int p = i >> 4, cg = i & 15;
        float4 a = *(const float4*)(qg + p * HD + cg * 4);
        qs[(cg * 4 + 0) * 200 + p] = a.x; qs[(cg * 4 + 1) * 200 + p] = a.y;
        qs[(cg * 4 + 2) * 200 + p] = a.z; qs[(cg * 4 + 3) * 200 + p] = a.w;
        float4 c = *(const float4*)(kg + p * HD + cg * 4);
        ks[(cg * 4 + 0) * 200 + p] = c.x; ks[(cg * 4 + 1) * 200 + p] = c.y;
        ks[(cg * 4 + 2) * 200 + p] = c.z; ks[(cg * 4 + 3) * 200 + p] = c.w;
    }
    __syncthreads();

    for (int i = tid; i < LW * WINS; i += 256) {
        int qi = i / WINS, kq = i % WINS;
        int iy = qi / WINS, ix = qi % WINS;
        const float* rh = rph + (iy - kq + 13) * HD;
        const float* rw = rpw + (ix - kq + 13) * HD;
        float ah = 0.f, aw = 0.f;
        #pragma unroll 8
        for (int c = 0; c < HD; c++) {
            float qv = qs[c * 200 + qi];
            ah += qv * rh[c];
            aw += qv * rw[c];
        }
        relh[i] = ah; relw[i] = aw;
    }
    __syncthreads();

    float* Pg = g_P + (size_t)wh * LL;
    for (int t = tid; t < 49 * 49; t += 256) {
        int ti = t / 49, tj = t % 49;
        int qi0 = ti * 4, ki0 = tj * 4;
        float acc[4][4] = {};
        #pragma unroll 8
        for (int c = 0; c < HD; c++) {
            float4 qv = *(float4*)&qs[c * 200 + qi0];
            float4 kv = *(float4*)&ks[c * 200 + ki0];
            acc[0][0] += qv.x * kv.x; acc[0][1] += qv.x * kv.y; acc[0][2] += qv.x * kv.z; acc[0][3] += qv.x * kv.w;
            acc[1][0] += qv.y * kv.x; acc[1][1] += qv.y * kv.y; acc[1][2] += qv.y * kv.z; acc[1][3] += qv.y * kv.w;
            acc[2][0] += qv.z * kv.x; acc[2][1] += qv.z * kv.y; acc[2][2] += qv.z * kv.z; acc[2][3] += qv.z * kv.w;
            acc[3][0] += qv.w * kv.x; acc[3][1] += qv.w * kv.y; acc[3][2] += qv.w * kv.z; acc[3][3] += qv.w * kv.w;
        }
        #pragma unroll
        for (int i = 0; i < 4; i++) {
            int qi = qi0 + i;
            float4 sv;
            float* svp = (float*)&sv;
            #pragma unroll
            for (int j = 0; j < 4; j++) {
                int ki = ki0 + j;
                int ky = ki / WINS, kx = ki % WINS;
                svp[j] = acc[i][j] * ATT_SCALE + relh[qi * WINS + ky] + relw[qi * WINS + kx];
            }
            *(float4*)(Pg + (size_t)qi * LW + ki0) = sv;
        }
    }
}

// ------- fused softmax + P@V: P tile and V both live in shared memory ------
// smem: vs[196*64] then Ps[196*196]. One block per (window, head).
__global__ void av_kernel()
{
    extern __shared__ float sm[];
    float* vs = sm;              // [196][64]
    float* Ps = sm + LW * HD;    // [196][196]
    int wh = blockIdx.x;
    int tid = threadIdx.x;
    const float* vg = g_v + (size_t)wh * LW * HD;
    const float* Pg = g_P + (size_t)wh * LL;

    for (int i = tid; i < LW * HD / 4; i += 256)
        ((float4*)vs)[i] = ((const float4*)vg)[i];
    for (int i = tid; i < LL / 4; i += 256)
        ((float4*)Ps)[i] = ((const float4*)Pg)[i];
    __syncthreads();

    // in-smem row softmax: one warp per row
    int warp = tid >> 5, lane = tid & 31;
    for (int r = warp; r < LW; r += 8) {
        float* row = Ps + r * LW;
        float v[7];
        float mx = -1e30f;
        #pragma unroll
        for (int j = 0; j < 7; j++) {
            int idx = lane + 32 * j;
            v[j] = (idx < LW) ? row[idx] : -1e30f;
            mx = fmaxf(mx, v[j]);
        }
        #pragma unroll
        for (int o = 16; o > 0; o >>= 1) mx = fmaxf(mx, __shfl_xor_sync(~0u, mx, o));
        float s = 0.f;
        #pragma unroll
        for (int j = 0; j < 7; j++) { v[j] = expf(v[j] - mx); s += v[j]; }
        #pragma unroll
        for (int o = 16; o > 0; o >>= 1) s += __shfl_xor_sync(~0u, s, o);
        float inv = 1.0f / s;
        #pragma unroll
        for (int j = 0; j < 7; j++) {
            int idx = lane + 32 * j;
            if (idx < LW) row[idx] = v[j] * inv;
        }
    }
    __syncthreads();

    if (tid < 196) {
        int qt = tid >> 2, dq = tid & 3;
        int qi0 = qt * 4, d0 = dq * 16;
        float4 acc[4][4] = {};
        for (int ki = 0; ki < LW; ki++) {
            float p0 = Ps[(qi0 + 0) * LW + ki];
            float p1 = Ps[(qi0 + 1) * LW + ki];
            float p2 = Ps[(qi0 + 2) * LW + ki];
            float p3 = Ps[(qi0 + 3) * LW + ki];
            const float4* vrow = (const float4*)(vs + ki * HD + d0);
            #pragma unroll
            for (int j = 0; j < 4; j++) {
                float4 vv = vrow[j];
                acc[0][j].x += p0 * vv.x; acc[0][j].y += p0 * vv.y; acc[0][j].z += p0 * vv.z; acc[0][j].w += p0 * vv.w;
                acc[1][j].x += p1 * vv.x; acc[1][j].y += p1 * vv.y; acc[1][j].z += p1 * vv.z; acc[1][j].w += p1 * vv.w;
                acc[2][j].x += p2 * vv.x; acc[2][j].y += p2 * vv.y; acc[2][j].z += p2 * vv.z; acc[2][j].w += p2 * vv.w;
                acc[3][j].x += p3 * vv.x; acc[3][j].y += p3 * vv.y; acc[3][j].z += p3 * vv.z; acc[3][j].w += p3 * vv.w;
            }
        }
        int wdx = wh / NHEADS, h = wh % NHEADS;
        #pragma unroll
        for (int i = 0; i < 4; i++) {
            size_t t2 = (size_t)wdx * LW + qi0 + i;
            float* orow = g_attnout + t2 * DIMC + h * HD + d0;
            #pragma unroll
            for (int j = 0; j < 4; j++)
                *(float4*)(orow + 4 * j) = acc[i][j];
        }
    }
}

// ---------------- launch ----------------------------------------------------
extern "C" void kernel_launch(void* const* d_in, const int* in_sizes, int n_in,
                              void* d_out, int out_size)
{
    (void)in_sizes; (void)n_in; (void)out_size;
    const float* x      = (const float*)d_in[0];
    const float* qkv_w  = (const float*)d_in[1];
    const float* qkv_b  = (const float*)d_in[2];
    const float* proj_w = (const float*)d_in[3];
    const float* proj_b = (const float*)d_in[4];
    const float* rph    = (const float*)d_in[5];
    const float* rpw    = (const float*)d_in[6];
    const float* n1w    = (const float*)d_in[7];
    const float* n1b    = (const float*)d_in[8];
    const float* n2w    = (const float*)d_in[9];
    const float* n2b    = (const float*)d_in[10];
    const float* fc1w   = (const float*)d_in[11];
    const float* fc1b   = (const float*)d_in[12];
    const float* fc2w   = (const float*)d_in[13];
    const float* fc2b   = (const float*)d_in[14];
    float* out = (float*)d_out;

    cudaFuncSetAttribute(score_kernel, cudaFuncAttributeMaxDynamicSharedMemorySize, SCORE_SMEM);
    cudaFuncSetAttribute(av_kernel,    cudaFuncAttributeMaxDynamicSharedMemorySize, AV_SMEM);

    void* p;
    cudaGetSymbolAddress(&p, g_xln);     float* xln  = (float*)p;
    cudaGetSymbolAddress(&p, g_attnout); float* ao   = (float*)p;
    cudaGetSymbolAddress(&p, g_x2);      float* x2p  = (float*)p;
    cudaGetSymbolAddress(&p, g_h1);      float* h1p  = (float*)p;

    // 1. LN1 (pixel order -> windowed token order)
    ln_kernel<<<TOK, 128>>>(x, n1w, n1b, xln, 1);
    // 2. QKV GEMM [112896,384]@[384,1152], scatter to head-major q/k/v
    sgemm<1><<<dim3(1152 / 128, TOK / 128), 256>>>(xln, qkv_w, qkv_b, nullptr, TOK, 1152, DIMC, nullptr);
    // 3. scores + rel pos (raw, pre-softmax)
    score_kernel<<<WH, 256, SCORE_SMEM>>>(rph, rpw);
    // 4. fused softmax + P@V
    av_kernel<<<WH, 256, AV_SMEM>>>();
    // 5. proj + residual, unwindow -> g_x2 (pixel order)
    sgemm<2><<<dim3(DIMC / 128, TOK / 128), 256>>>(ao, proj_w, proj_b, nullptr, TOK, DIMC, DIMC, x);
    // 6. LN2 (pixel order, reuse g_xln as output)
    ln_kernel<<<TOK, 128>>>(x2p, n2w, n2b, xln, 0);
    // 7. fc1 + gelu
    sgemm<3><<<dim3(HIDDEN / 128, TOK / 128), 256>>>(xln, fc1w, fc1b, h1p, TOK, HIDDEN, DIMC, nullptr);
    // 8. fc2 + residual -> out
    sgemm<4><<<dim3(DIMC / 128, TOK / 128), 256>>>(h1p, fc2w, fc2b, out, TOK, DIMC, HIDDEN, x2p);
}